// round 4
// baseline (speedup 1.0000x reference)
#include <cuda_runtime.h>
#include <cstdint>

#define T_STEPS 2048
#define BATCH   1024
#define INPUT   4
#define HID     10
#define OUTF    4
#define CHUNK   16          // timesteps staged per cp.async chunk
#define BPB     16          // batches per block (8 warps * 2)
#define THREADS 256

// HW tanh (MUFU, lat ~16) — replaces EX2+RCP chains
__device__ __forceinline__ float htanh(float x) {
    float y;
    asm("tanh.approx.f32 %0, %1;" : "=f"(y) : "f"(x));
    return y;
}
__device__ __forceinline__ float sigf(float x) {
    // sigmoid(x) = 0.5 * tanh(x/2) + 0.5
    return fmaf(0.5f, htanh(0.5f * x), 0.5f);
}

__device__ __forceinline__ void cp_async16(void* dst, const void* src) {
    unsigned d = (unsigned)__cvta_generic_to_shared(dst);
    asm volatile("cp.async.ca.shared.global [%0], [%1], 16;\n" :: "r"(d), "l"(src));
}
__device__ __forceinline__ void cp_commit() {
    asm volatile("cp.async.commit_group;\n" ::: "memory");
}
__device__ __forceinline__ void cp_wait1() {
    asm volatile("cp.async.wait_group 1;\n" ::: "memory");
}

__global__ void __launch_bounds__(THREADS, 1)
lstm_persistent_kernel(const float* __restrict__ x,
                       const float* __restrict__ h0,
                       const float* __restrict__ c0,
                       const float* __restrict__ W_ih,
                       const float* __restrict__ W_hh,
                       const float* __restrict__ b_ih,
                       const float* __restrict__ b_hh,
                       const float* __restrict__ W_fc,
                       const float* __restrict__ b_fc,
                       float* __restrict__ out,
                       int write_state)
{
    __shared__ float4 sx[2][CHUNK][BPB];

    const int tid  = threadIdx.x;
    const int warp = tid >> 5;
    const int lane = tid & 31;
    const int half = lane >> 4;      // 0 or 1: which batch in the warp
    const int jj   = lane & 15;      // lane id within 16-lane group
    const int j    = (jj < HID) ? jj : (HID - 1);  // clamped hidden index

    const int gbase = blockIdx.x * BPB;
    const int bb    = warp * 2 + half;         // batch index within block 0..15
    const int batch = gbase + bb;              // global batch 0..1023

    // ---- load per-lane weights into registers (once) ----
    float wih[4][INPUT], whh[4][HID], bias[4];
#pragma unroll
    for (int g = 0; g < 4; g++) {
        const int row = g * HID + j;
#pragma unroll
        for (int i = 0; i < INPUT; i++) wih[g][i] = W_ih[row * INPUT + i];
#pragma unroll
        for (int k = 0; k < HID; k++)   whh[g][k] = W_hh[row * HID + k];
        bias[g] = b_ih[row] + b_hh[row];
    }
    const int jo = (jj < OUTF) ? jj : 0;
    float wfc[HID], bfc = b_fc[jo];
#pragma unroll
    for (int k = 0; k < HID; k++) wfc[k] = W_fc[jo * HID + k];

    // ---- state ----
    float h_all[HID];
#pragma unroll
    for (int k = 0; k < HID; k++) h_all[k] = h0[batch * HID + k];
    float c = c0[batch * HID + j];

    const float4* x4 = reinterpret_cast<const float4*>(x);
    const int tt = tid >> 4;   // 0..15 : timestep within chunk
    const int bx = tid & 15;   // 0..15 : batch within block

    // prefetch chunk 0
    cp_async16(&sx[0][tt][bx], x4 + (size_t)(0 * CHUNK + tt) * BATCH + gbase + bx);
    cp_commit();

    const int NCH = T_STEPS / CHUNK;   // 128
    for (int ch = 0; ch < NCH; ch++) {
        if (ch + 1 < NCH) {
            cp_async16(&sx[(ch + 1) & 1][tt][bx],
                       x4 + (size_t)((ch + 1) * CHUNK + tt) * BATCH + gbase + bx);
        }
        cp_commit();
        cp_wait1();          // chunk `ch` resident
        __syncthreads();

        const int buf = ch & 1;
#pragma unroll 2
        for (int s = 0; s < CHUNK; s++) {
            const float4 xv = sx[buf][s][bb];

            float gate[4];
#pragma unroll
            for (int g = 0; g < 4; g++) {
                // two accumulators to halve the dependency chain
                float a  = fmaf(xv.x, wih[g][0], bias[g]);
                float b2 = xv.y * wih[g][1];
                a  = fmaf(xv.z, wih[g][2], a);
                b2 = fmaf(xv.w, wih[g][3], b2);
#pragma unroll
                for (int k = 0; k < HID; k += 2) {
                    a  = fmaf(h_all[k],     whh[g][k],     a);
                    b2 = fmaf(h_all[k + 1], whh[g][k + 1], b2);
                }
                gate[g] = a + b2;
            }

            const float ig = sigf(gate[0]);
            const float fg = sigf(gate[1]);
            const float gg = htanh(gate[2]);
            const float og = sigf(gate[3]);

            c = fmaf(fg, c, ig * gg);
            const float hn = og * htanh(c);

            // broadcast new h across the 16-lane group (serves FC now and gates next step)
#pragma unroll
            for (int k = 0; k < HID; k++)
                h_all[k] = __shfl_sync(0xffffffffu, hn, k, 16);

            if (jj < OUTF) {
                float a  = bfc;
                float b2 = 0.0f;
#pragma unroll
                for (int k = 0; k < HID; k += 2) {
                    a  = fmaf(h_all[k],     wfc[k],     a);
                    b2 = fmaf(h_all[k + 1], wfc[k + 1], b2);
                }
                const int t = ch * CHUNK + s;
                out[((size_t)t * BATCH + batch) * OUTF + jj] = a + b2;
            }
        }
        __syncthreads();   // everyone done with buf before it gets overwritten
    }

    // ---- final states (hT, cT) appended after `out` in the flattened pytree ----
    if (write_state && jj < HID) {
        const size_t off = (size_t)T_STEPS * BATCH * OUTF;
        out[off + (size_t)batch * HID + jj] = h_all[jj];
        out[off + (size_t)BATCH * HID + (size_t)batch * HID + jj] = c;
    }
}

extern "C" void kernel_launch(void* const* d_in, const int* in_sizes, int n_in,
                              void* d_out, int out_size) {
    const float* x    = (const float*)d_in[0];
    const float* h0   = (const float*)d_in[1];
    const float* c0   = (const float*)d_in[2];
    const float* W_ih = (const float*)d_in[3];
    const float* W_hh = (const float*)d_in[4];
    const float* b_ih = (const float*)d_in[5];
    const float* b_hh = (const float*)d_in[6];
    const float* W_fc = (const float*)d_in[7];
    const float* b_fc = (const float*)d_in[8];
    float* out = (float*)d_out;

    const long long need_state = (long long)T_STEPS * BATCH * OUTF + 2LL * BATCH * HID;
    const int write_state = (out_size >= need_state) ? 1 : 0;

    lstm_persistent_kernel<<<BATCH / BPB, THREADS>>>(
        x, h0, c0, W_ih, W_hh, b_ih, b_hh, W_fc, b_fc, out, write_state);
}

// round 5
// speedup vs baseline: 2.1934x; 2.1934x over previous
#include <cuda_runtime.h>
#include <cstdint>

#define T_STEPS 2048
#define BATCH   1024
#define INPUT   4
#define HID     10
#define OUTF    4
#define CHUNK   16          // timesteps staged per cp.async chunk
#define BPB     8           // batches per block (4 warps * 2) -> 128 blocks, 1 warp/SMSP
#define THREADS 128

typedef unsigned long long u64;

// ---- Blackwell packed f32x2 helpers ----
__device__ __forceinline__ u64 pk2(float lo, float hi) {
    u64 r; asm("mov.b64 %0, {%1,%2};" : "=l"(r) : "f"(lo), "f"(hi)); return r;
}
__device__ __forceinline__ void up2(u64 v, float& lo, float& hi) {
    asm("mov.b64 {%0,%1}, %2;" : "=f"(lo), "=f"(hi) : "l"(v));
}
__device__ __forceinline__ u64 ffma2(u64 a, u64 b, u64 c) {
    u64 d; asm("fma.rn.f32x2 %0, %1, %2, %3;" : "=l"(d) : "l"(a), "l"(b), "l"(c)); return d;
}
__device__ __forceinline__ u64 fadd2(u64 a, u64 b) {
    u64 d; asm("add.rn.f32x2 %0, %1, %2;" : "=l"(d) : "l"(a), "l"(b)); return d;
}

// HW tanh (MUFU) — rel err ~5e-4 worst case, damped by the contractive recurrence
__device__ __forceinline__ float htanh(float x) {
    float y; asm("tanh.approx.f32 %0, %1;" : "=f"(y) : "f"(x)); return y;
}
__device__ __forceinline__ float sigf(float x) {
    return fmaf(0.5f, htanh(0.5f * x), 0.5f);   // sigmoid via tanh
}

__device__ __forceinline__ void cp_async16(void* dst, const void* src) {
    unsigned d = (unsigned)__cvta_generic_to_shared(dst);
    asm volatile("cp.async.ca.shared.global [%0], [%1], 16;\n" :: "r"(d), "l"(src));
}
__device__ __forceinline__ void cp_commit() {
    asm volatile("cp.async.commit_group;\n" ::: "memory");
}
__device__ __forceinline__ void cp_wait1() {
    asm volatile("cp.async.wait_group 1;\n" ::: "memory");
}

__global__ void __launch_bounds__(THREADS, 1)
lstm_persistent_kernel(const float* __restrict__ x,
                       const float* __restrict__ h0,
                       const float* __restrict__ c0,
                       const float* __restrict__ W_ih,
                       const float* __restrict__ W_hh,
                       const float* __restrict__ b_ih,
                       const float* __restrict__ b_hh,
                       const float* __restrict__ W_fc,
                       const float* __restrict__ b_fc,
                       float* __restrict__ out,
                       int write_state)
{
    __shared__ float4 sx[2][CHUNK][BPB];

    const int tid  = threadIdx.x;
    const int warp = tid >> 5;
    const int lane = tid & 31;
    const int half = lane >> 4;      // which batch in the warp
    const int jj   = lane & 15;      // lane id within 16-lane group
    const int j    = (jj < HID) ? jj : (HID - 1);  // clamped hidden index

    const int gbase = blockIdx.x * BPB;
    const int bb    = warp * 2 + half;         // batch index within block 0..7
    const int batch = gbase + bb;              // global batch 0..1023

    // ---- pack per-lane weights: pair (i,f) gates and (g,o) gates as f32x2 ----
    // rows: i=j, f=10+j, g=20+j, o=30+j
    u64 wih_if[INPUT], wih_go[INPUT], whh_if[HID], whh_go[HID];
#pragma unroll
    for (int k = 0; k < INPUT; k++) {
        wih_if[k] = pk2(W_ih[(0*HID + j)*INPUT + k], W_ih[(1*HID + j)*INPUT + k]);
        wih_go[k] = pk2(W_ih[(2*HID + j)*INPUT + k], W_ih[(3*HID + j)*INPUT + k]);
    }
#pragma unroll
    for (int k = 0; k < HID; k++) {
        whh_if[k] = pk2(W_hh[(0*HID + j)*HID + k], W_hh[(1*HID + j)*HID + k]);
        whh_go[k] = pk2(W_hh[(2*HID + j)*HID + k], W_hh[(3*HID + j)*HID + k]);
    }
    const u64 bias_if = pk2(b_ih[0*HID+j] + b_hh[0*HID+j], b_ih[1*HID+j] + b_hh[1*HID+j]);
    const u64 bias_go = pk2(b_ih[2*HID+j] + b_hh[2*HID+j], b_ih[3*HID+j] + b_hh[3*HID+j]);

    // FC weights packed as {w, 0}: hi half accumulates zeros
    const int jo = (jj < OUTF) ? jj : 0;
    const float bfc = b_fc[jo];
    u64 wfcd[HID];
#pragma unroll
    for (int k = 0; k < HID; k++) wfcd[k] = pk2(W_fc[jo * HID + k], 0.0f);

    // ---- state: h duplicated {h,h} per unit; c scalar per lane ----
    u64 hd[HID];
#pragma unroll
    for (int k = 0; k < HID; k++) {
        const float hv = h0[batch * HID + k];
        hd[k] = pk2(hv, hv);
    }
    float c = c0[batch * HID + j];

    const float4* x4 = reinterpret_cast<const float4*>(x);
    const int tt = tid >> 3;   // 0..15 : timestep within chunk
    const int bx = tid & 7;    // 0..7  : batch within block

    // prefetch chunk 0
    cp_async16(&sx[0][tt][bx], x4 + (size_t)(0 * CHUNK + tt) * BATCH + gbase + bx);
    cp_commit();

    const u64 ZERO = 0ull;   // {0.f, 0.f}

    const int NCH = T_STEPS / CHUNK;   // 128
    for (int ch = 0; ch < NCH; ch++) {
        if (ch + 1 < NCH) {
            cp_async16(&sx[(ch + 1) & 1][tt][bx],
                       x4 + (size_t)((ch + 1) * CHUNK + tt) * BATCH + gbase + bx);
        }
        cp_commit();
        cp_wait1();          // chunk `ch` resident
        __syncthreads();

        const int buf = ch & 1;
#pragma unroll 2
        for (int s = 0; s < CHUNK; s++) {
            const float4 xv = sx[buf][s][bb];
            const u64 xd0 = pk2(xv.x, xv.x);
            const u64 xd1 = pk2(xv.y, xv.y);
            const u64 xd2 = pk2(xv.z, xv.z);
            const u64 xd3 = pk2(xv.w, xv.w);

            // gate dots: 28 FFMA2 total (two gate-pairs, two accumulators each)
            u64 aif = ffma2(xd0, wih_if[0], bias_if);
            u64 bif = ffma2(xd1, wih_if[1], ZERO);
            u64 ago = ffma2(xd0, wih_go[0], bias_go);
            u64 bgo = ffma2(xd1, wih_go[1], ZERO);
            aif = ffma2(xd2, wih_if[2], aif);
            bif = ffma2(xd3, wih_if[3], bif);
            ago = ffma2(xd2, wih_go[2], ago);
            bgo = ffma2(xd3, wih_go[3], bgo);
#pragma unroll
            for (int k = 0; k < HID; k += 2) {
                aif = ffma2(hd[k],     whh_if[k],     aif);
                bif = ffma2(hd[k + 1], whh_if[k + 1], bif);
                ago = ffma2(hd[k],     whh_go[k],     ago);
                bgo = ffma2(hd[k + 1], whh_go[k + 1], bgo);
            }

            float ipre, fpre, gpre, opre;
            up2(fadd2(aif, bif), ipre, fpre);
            up2(fadd2(ago, bgo), gpre, opre);

            const float ig = sigf(ipre);
            const float fg = sigf(fpre);
            const float gg = htanh(gpre);
            const float og = sigf(opre);

            c = fmaf(fg, c, ig * gg);
            const float hn = og * htanh(c);

            // broadcast new h across the 16-lane group, re-duplicated {h,h}
#pragma unroll
            for (int k = 0; k < HID; k++) {
                const float hk = __shfl_sync(0xffffffffu, hn, k, 16);
                hd[k] = pk2(hk, hk);
            }

            if (jj < OUTF) {
                u64 fa = ffma2(hd[0], wfcd[0], ZERO);
                u64 fb = ffma2(hd[1], wfcd[1], ZERO);
#pragma unroll
                for (int k = 2; k < HID; k += 2) {
                    fa = ffma2(hd[k],     wfcd[k],     fa);
                    fb = ffma2(hd[k + 1], wfcd[k + 1], fb);
                }
                float d0, d1;
                up2(fadd2(fa, fb), d0, d1);
                const int t = ch * CHUNK + s;
                out[((size_t)t * BATCH + batch) * OUTF + jj] = d0 + bfc;
            }
        }
        __syncthreads();   // everyone done with buf before it gets overwritten
    }

    // ---- final states (hT, cT) appended after `out` in the flattened pytree ----
    if (write_state && jj < HID) {
        float hlo, hhi;
        up2(hd[jj], hlo, hhi);
        const size_t off = (size_t)T_STEPS * BATCH * OUTF;
        out[off + (size_t)batch * HID + jj] = hlo;
        out[off + (size_t)BATCH * HID + (size_t)batch * HID + jj] = c;
    }
}

extern "C" void kernel_launch(void* const* d_in, const int* in_sizes, int n_in,
                              void* d_out, int out_size) {
    const float* x    = (const float*)d_in[0];
    const float* h0   = (const float*)d_in[1];
    const float* c0   = (const float*)d_in[2];
    const float* W_ih = (const float*)d_in[3];
    const float* W_hh = (const float*)d_in[4];
    const float* b_ih = (const float*)d_in[5];
    const float* b_hh = (const float*)d_in[6];
    const float* W_fc = (const float*)d_in[7];
    const float* b_fc = (const float*)d_in[8];
    float* out = (float*)d_out;

    const long long need_state = (long long)T_STEPS * BATCH * OUTF + 2LL * BATCH * HID;
    const int write_state = (out_size >= need_state) ? 1 : 0;

    lstm_persistent_kernel<<<BATCH / BPB, THREADS>>>(
        x, h0, c0, W_ih, W_hh, b_ih, b_hh, W_fc, b_fc, out, write_state);
}